// round 11
// baseline (speedup 1.0000x reference)
#include <cuda_runtime.h>
#include <cstdint>

// ---------------------------------------------------------------------------
// Compile-time CG instruction table (deterministic, mirrors _build_instructions)
// ---------------------------------------------------------------------------
constexpr int LMAX    = 3;
constexpr int DIM_IN  = 16;   // (LMAX+1)^2
constexpr int NCH     = 64;
constexpr int NC2     = NCH / 2;      // 32 float2 lanes per node
constexpr int MAXNNZ  = 600;

struct Tab {
    int mu1[MAXNNZ];
    int mu2[MAXNNZ];
    int mu3[MAXNNZ];
    int nnz;
    int dim_out;
};

constexpr Tab make_tab() {
    Tab t{};
    int idx = 0;
    int off3 = 0;
    for (int l1 = 0; l1 <= LMAX; ++l1) {
        for (int l2 = 0; l2 <= LMAX; ++l2) {
            int lo = (l1 > l2) ? (l1 - l2) : (l2 - l1);
            int hi = (l1 + l2 < LMAX) ? (l1 + l2) : LMAX;
            for (int l3 = lo; l3 <= hi; ++l3) {
                int k = (2 * l1 + 1 < 2 * l2 + 1) ? (2 * l1 + 1) : (2 * l2 + 1);
                for (int m3 = 0; m3 < 2 * l3 + 1; ++m3) {
                    for (int m1 = 0; m1 < k; ++m1) {
                        int m2 = (m1 + m3) % (2 * l2 + 1);
                        t.mu1[idx] = l1 * l1 + m1;
                        t.mu2[idx] = l2 * l2 + m2;
                        t.mu3[idx] = off3 + m3;
                        ++idx;
                    }
                }
                off3 += 2 * l3 + 1;
            }
        }
    }
    t.nnz = idx;
    t.dim_out = off3;
    return t;
}

// Host copy for constexpr analysis; device copy for in-kernel indexing.
constexpr Tab HTAB = make_tab();
__device__ constexpr Tab TAB = make_tab();

constexpr int NNZ     = 562;
constexpr int DIM_OUT = 156;
constexpr int NNZ4    = (NNZ + 3) / 4;   // 141 float4 groups
constexpr int NNZPAD  = NNZ4 * 4;        // 564
constexpr int OUT_TILE_BYTES = DIM_OUT * NCH * 4;   // 39936, 16B multiple
static_assert(HTAB.nnz == NNZ, "nnz mismatch");
static_assert(HTAB.dim_out == DIM_OUT, "dim_out mismatch");
static_assert(OUT_TILE_BYTES % 16 == 0, "bulk size must be 16B multiple");

// mu3-segment boundary closest to target (quarters write disjoint output rows)
constexpr int find_split(int target) {
    int best = 0, bestd = 1 << 30;
    for (int i = 1; i < NNZ; ++i) {
        if (HTAB.mu3[i] != HTAB.mu3[i - 1]) {
            int d = i - target; if (d < 0) d = -d;
            if (d < bestd) { bestd = d; best = i; }
        }
    }
    return best;
}
constexpr int S1 = find_split(NNZ / 4);
constexpr int S2 = find_split(NNZ / 2);
constexpr int S3 = find_split(3 * NNZ / 4);

// Usage bitmasks, evaluated entirely at host compile time (no device odr-use).
constexpr uint32_t x_mask(int lo, int hi) {
    uint32_t m = 0;
    for (int i = lo; i < hi; ++i) m |= (1u << HTAB.mu1[i]);
    return m;
}
constexpr uint32_t y_quad_mask(int lo, int hi) {
    uint32_t m = 0;
    for (int i = lo; i < hi; ++i) m |= (1u << (HTAB.mu2[i] / 4));
    return m;
}
constexpr uint32_t XM0 = x_mask(0,  S1),  YM0 = y_quad_mask(0,  S1);
constexpr uint32_t XM1 = x_mask(S1, S2),  YM1 = y_quad_mask(S1, S2);
constexpr uint32_t XM2 = x_mask(S2, S3),  YM2 = y_quad_mask(S2, S3);
constexpr uint32_t XM3 = x_mask(S3, NNZ), YM3 = y_quad_mask(S3, NNZ);

// ---------------------------------------------------------------------------
// Per-quarter worker: fully unrolled over instruction range [LO, HI).
// Accumulates mu3-sorted segments in a float2 (this thread's 2 channels) and
// flushes into the SMEM output staging tile (conflict-free: warp writes one
// contiguous 256B row slice).
// ---------------------------------------------------------------------------
template<int LO, int HI, uint32_t XM, uint32_t YM>
__device__ __forceinline__ void run_range(const float2* __restrict__ x2,
                                          const float*  __restrict__ yrow,
                                          const float4* __restrict__ cg_s4,
                                          float2*       __restrict__ out_s2)
{
    // y components (vector loads per used quad; CTA-wide broadcast)
    float ys[DIM_IN];
    const float4* y4 = reinterpret_cast<const float4*>(yrow);
    #pragma unroll
    for (int q = 0; q < 4; ++q) {
        if ((YM >> q) & 1u) {
            float4 v = __ldg(y4 + q);
            ys[4 * q + 0] = v.x;
            ys[4 * q + 1] = v.y;
            ys[4 * q + 2] = v.z;
            ys[4 * q + 3] = v.w;
        }
    }

    // x components used by this range (streaming: read once globally)
    float2 xs[DIM_IN];
    #pragma unroll
    for (int l = 0; l < DIM_IN; ++l)
        if ((XM >> l) & 1u)
            xs[l] = __ldcs(x2 + l * NC2);

    float a0 = 0.f, a1 = 0.f;

    constexpr int G0 = LO / 4;
    constexpr int G1 = (HI + 3) / 4;

    #pragma unroll
    for (int g = G0; g < G1; ++g) {
        const float4 c4v = cg_s4[g];      // broadcast LDS.128
        const float cv[4] = { c4v.x, c4v.y, c4v.z, c4v.w };
        #pragma unroll
        for (int j = 0; j < 4; ++j) {
            const int i = 4 * g + j;      // compile-time under full unroll
            if (i >= LO && i < HI) {
                const float  wv = cv[j] * ys[TAB.mu2[i]];
                const float2 v  = xs[TAB.mu1[i]];   // compile-time reg index
                a0 = fmaf(wv, v.x, a0);
                a1 = fmaf(wv, v.y, a1);
                if (i + 1 == HI || TAB.mu3[i + 1] != TAB.mu3[i]) {  // folds
                    out_s2[TAB.mu3[i] * NC2] = make_float2(a0, a1);  // STS.64
                    a0 = a1 = 0.f;
                }
            }
        }
    }
}

// ---------------------------------------------------------------------------
// Kernel: 1 node per CTA. 128 threads = 4 warps; warp w = instruction-quarter w,
// its 32 lanes = float2 channel-slots (warp-uniform, no divergence).
// Output staged in SMEM (40KB contiguous tile == gmem layout), then emitted as
// ONE cp.async.bulk shared->global per node: perfectly sequential 40KB DRAM
// write bursts, no STG issue cost, async-proxy drain overlapped by the other
// 4 resident CTAs (42.2KB smem -> 5 CTAs/SM).
// ---------------------------------------------------------------------------
constexpr int TPB = 128;

__global__ __launch_bounds__(TPB)
void tp_kernel(const float* __restrict__ x,
               const float* __restrict__ y,
               const float* __restrict__ cg,
               float*       __restrict__ out)
{
    __shared__ float  out_s[DIM_OUT * NCH];   // 39936 B staging tile
    __shared__ float4 cg_s4[NNZ4];            // 2256 B

    // Stage cg into shared (zero-pad tail)
    for (int t = threadIdx.x; t < NNZPAD; t += TPB)
        reinterpret_cast<float*>(cg_s4)[t] = (t < NNZ) ? __ldg(&cg[t]) : 0.f;
    __syncthreads();

    const int quarter = threadIdx.x >> 5;     // warp id = instruction quarter
    const int lane    = threadIdx.x & 31;     // float2 lane: channels 2l, 2l+1
    const int node    = blockIdx.x;

    const float2* x2 = reinterpret_cast<const float2*>(x)
                     + (size_t)node * DIM_IN * NC2 + lane;
    const float* yrow = y + (size_t)node * DIM_IN;
    float2* out_s2 = reinterpret_cast<float2*>(out_s) + lane;

    switch (quarter) {
        case 0: run_range<0,  S1,  XM0, YM0>(x2, yrow, cg_s4, out_s2); break;
        case 1: run_range<S1, S2,  XM1, YM1>(x2, yrow, cg_s4, out_s2); break;
        case 2: run_range<S2, S3,  XM2, YM2>(x2, yrow, cg_s4, out_s2); break;
        default: run_range<S3, NNZ, XM3, YM3>(x2, yrow, cg_s4, out_s2); break;
    }

    __syncthreads();
    // Order generic-proxy STS before the async-proxy bulk read of smem.
    asm volatile("fence.proxy.async.shared::cta;" ::: "memory");

    if (threadIdx.x == 0) {
        uint32_t saddr;
        asm("{ .reg .u64 t; cvta.to.shared.u64 t, %1; cvt.u32.u64 %0, t; }"
            : "=r"(saddr) : "l"(out_s));
        float* gdst = out + (size_t)node * DIM_OUT * NCH;
        asm volatile(
            "cp.async.bulk.global.shared::cta.bulk_group [%0], [%1], %2;"
            :: "l"(gdst), "r"(saddr), "r"((int)OUT_TILE_BYTES) : "memory");
        asm volatile("cp.async.bulk.commit_group;" ::: "memory");
        // Hold the CTA alive (smem must stay valid) until the bulk store lands.
        asm volatile("cp.async.bulk.wait_group 0;" ::: "memory");
    }
}

// ---------------------------------------------------------------------------
// Launch: inputs per setup_inputs order: x, y, cg_coeffs, mu_1, mu_2, mu_3, ...
// ---------------------------------------------------------------------------
extern "C" void kernel_launch(void* const* d_in, const int* in_sizes, int n_in,
                              void* d_out, int out_size)
{
    const float* x   = (const float*)d_in[0];
    const float* y   = (const float*)d_in[1];
    const float* cg  = (const float*)d_in[2];
    float*       out = (float*)d_out;

    const int n_nodes = in_sizes[1] / DIM_IN;   // y has [N, 16]

    tp_kernel<<<n_nodes, TPB>>>(x, y, cg, out);
}